// round 6
// baseline (speedup 1.0000x reference)
#include <cuda_runtime.h>
#include <cstdint>

// CapsuleRouting streaming, 2 CTAs/SM:
//  - CTA = (b, x-tile of 4); grid 288 = 2 CTAs per SM (phase overlap keeps HBM fed)
//  - 3 passes over u, 4-stage cp.async pipeline, 1 __syncthreads per chunk
//  - softmax over C via 16-lane shuffles (no max-subtraction; |r| small)
//  - `a` input cancels in softmax -> ignored

#define C_N    16
#define P_N    16
#define F2     144
#define XT     4
#define NTILE  36            // 144 / XT
#define BCH    4
#define NCHUNK 36            // 144 / BCH
#define PLANE  68            // P_N*XT + 4 pad
#define NSTG   4

#define STG_FLOATS (BCH * C_N * PLANE)        // 4352
#define U_S_OFF    0
#define U_S_SIZE   (NSTG * STG_FLOATS)        // 17408
#define R_S_OFF    (U_S_OFF + U_S_SIZE)
#define R_S_SIZE   (144 * C_N * XT)           // 9216
#define V_S_OFF    (R_S_OFF + R_S_SIZE)
#define V_S_SIZE   (C_N * PLANE)              // 1088
#define SMEM_FLOATS (V_S_OFF + V_S_SIZE)      // 27712
#define SMEM_BYTES  (SMEM_FLOATS * 4)         // 110848  -> 2 CTAs/SM

#define V_ELEMS (8 * C_N * P_N * F2)          // 294912

__device__ __forceinline__ void cp_async16(float* smem_dst, const float* gmem_src) {
    unsigned s = (unsigned)__cvta_generic_to_shared(smem_dst);
    asm volatile("cp.async.cg.shared.global [%0], [%1], 16;" :: "r"(s), "l"(gmem_src));
}

// one B-chunk = 4B * 16C * 16p rows of 16B = 16 KB
__device__ __forceinline__ void prefetch_chunk(const float* __restrict__ ub,
                                               float* __restrict__ u_s,
                                               int ch, int stg, int x0, int t) {
    float* dst = u_s + stg * STG_FLOATS;
    int B0 = ch * BCH;
#pragma unroll
    for (int k = 0; k < 4; k++) {
        int q  = t + k * 256;          // 0..1023
        int Bl = q >> 8;
        int Cl = (q >> 4) & 15;
        int pl = q & 15;
        const float* g = ub + ((size_t)((B0 + Bl) * C_N + Cl) * P_N + pl) * F2 + x0;
        cp_async16(dst + (Bl * C_N + Cl) * PLANE + pl * XT, g);
    }
    asm volatile("cp.async.commit_group;");
}

__global__ void __launch_bounds__(256, 2)
caps_route_kernel(const float* __restrict__ u, float* __restrict__ out) {
    extern __shared__ float sm[];
    float* u_s = sm + U_S_OFF;
    float* r_s = sm + R_S_OFF;
    float* v_s = sm + V_S_OFF;
    float* tmp = sm + U_S_OFF;           // aliases stage 0 (safe at pass tail)

    const int t    = threadIdx.x;
    const int bid  = blockIdx.x;
    const int b    = bid / NTILE;
    const int tile = bid - b * NTILE;
    const int x0   = tile * XT;

    const float* ub = u + (size_t)b * 144 * C_N * P_N * F2;

    // main mapping: t = Bl*64 + z*16 + Cc  (C in 16-lane shuffle groups)
    const int Bl = t >> 6;
    const int z  = (t >> 4) & 3;
    const int Cc = t & 15;
    const int ubase_off = (Bl * C_N + Cc) * PLANE + z;

    // squash mapping: t = Cc2*16 + z2*4 + pg  (pg in low 2 bits -> warp reduce)
    const int Cc2 = t >> 4;
    const int z2  = (t >> 2) & 3;
    const int pg  = t & 3;

    float sreg[16], vreg[16];

    for (int pass = 0; pass < 3; pass++) {
#pragma unroll
        for (int i = 0; i < 16; i++) sreg[i] = 0.f;
        if (pass) {
#pragma unroll
            for (int p = 0; p < 16; p++) vreg[p] = v_s[Cc * PLANE + p * XT + z];
        }

#pragma unroll
        for (int k = 0; k < NSTG - 1; k++) prefetch_chunk(ub, u_s, k, k, x0, t);

        for (int ch = 0; ch < NCHUNK; ch++) {
            if      (ch < NCHUNK - 2)  asm volatile("cp.async.wait_group 2;");
            else if (ch == NCHUNK - 2) asm volatile("cp.async.wait_group 1;");
            else                       asm volatile("cp.async.wait_group 0;");
            __syncthreads();   // chunk ch visible; stage (ch+3)&3 free

            if (ch + NSTG - 1 < NCHUNK)
                prefetch_chunk(ub, u_s, ch + NSTG - 1, (ch + NSTG - 1) & 3, x0, t);

            const float* base = u_s + (ch & 3) * STG_FLOATS + ubase_off;
            float ureg[16];
#pragma unroll
            for (int p = 0; p < 16; p++) ureg[p] = base[p * XT];

            if (pass == 0) {
#pragma unroll
                for (int p = 0; p < 16; p++) sreg[p] += ureg[p];
            } else {
                float dot = 0.f;
#pragma unroll
                for (int p = 0; p < 16; p++) dot = fmaf(ureg[p], vreg[p], dot);

                const int ridx = ((ch * BCH + Bl) * C_N + Cc) * XT + z;
                float rv = (pass == 1) ? dot : (r_s[ridx] + dot);
                r_s[ridx] = rv;

                float e = __expf(rv), ss = e;
#pragma unroll
                for (int m = 1; m < 16; m <<= 1)
                    ss += __shfl_xor_sync(0xffffffffu, ss, m);
                const float cc = __fdividef(e, ss);
#pragma unroll
                for (int p = 0; p < 16; p++) sreg[p] = fmaf(cc, ureg[p], sreg[p]);
            }
        }

        // ---- squash (tmp aliases stage 0; all async drained, stage 0 idle)
        const float w = (pass == 0) ? 0.0625f : 1.0f;
#pragma unroll
        for (int p = 0; p < 16; p++)
            tmp[(Bl * C_N + Cc) * PLANE + p * XT + z] = sreg[p] * w;
        __syncthreads();

        float sp[4];
        float snp = 0.f;
#pragma unroll
        for (int k = 0; k < 4; k++) {
            const int p = pg * 4 + k;
            float s = 0.f;
#pragma unroll
            for (int B2 = 0; B2 < 4; B2++)
                s += tmp[(B2 * C_N + Cc2) * PLANE + p * XT + z2];
            sp[k] = s;
            snp = fmaf(s, s, snp);
        }
        // reduce over pg (bits 0-1 of t)
        snp += __shfl_xor_sync(0xffffffffu, snp, 1);
        snp += __shfl_xor_sync(0xffffffffu, snp, 2);
        const float scale = sqrtf(snp) / (1.f + snp);

        __syncthreads();   // tmp reads done before stage 0 reused next pass

#pragma unroll
        for (int k = 0; k < 4; k++)
            v_s[Cc2 * PLANE + (pg * 4 + k) * XT + z2] = sp[k] * scale;

        if (pass == 2 && pg == 0)
            out[(size_t)V_ELEMS + ((size_t)(b * C_N + Cc2)) * F2 + x0 + z2] =
                snp / (1.f + snp);
        __syncthreads();
    }

    // coalesced v write: 256 rows of (C,p), one float4 each
    {
        const int Cr = t >> 4, pr = t & 15;
        const float4* src = (const float4*)(v_s + Cr * PLANE + pr * XT);
        float4* dst = (float4*)(out + (((size_t)(b * C_N + Cr)) * P_N + pr) * F2 + x0);
        dst[0] = src[0];
    }
}

extern "C" void kernel_launch(void* const* d_in, const int* in_sizes, int n_in,
                              void* d_out, int out_size) {
    const float* u = (const float*)d_in[0];   // (8,144,16,16,12,12) f32
    float* out = (float*)d_out;               // v (8,16,16,144) then a_out (8,16,144)

    cudaFuncSetAttribute(caps_route_kernel,
                         cudaFuncAttributeMaxDynamicSharedMemorySize, SMEM_BYTES);
    caps_route_kernel<<<8 * NTILE, 256, SMEM_BYTES>>>(u, out);
}

// round 7
// speedup vs baseline: 1.1336x; 1.1336x over previous
#include <cuda_runtime.h>
#include <cstdint>

// CapsuleRouting, R6: XT=8 sector-exact + 2 CTAs/SM via B-split cluster(2)
//  - r eliminated: logits linear in v -> pass2 dots against w = v0+v1
//  - CTA = (b, x-tile of 8, B-half of 72); 288 CTAs = 1 wave at 2/SM
//  - per-pass cross-CTA s-reduction (4KB each way) via DSMEM, C-half owners
//  - softmax over C via 16-lane shuffles (no max-subtraction; logits small)

#define C_N    16
#define P_N    16
#define F2     144
#define XT     8
#define NTILE  18            // 144 / XT
#define BHALF  72
#define BCH    2
#define NCHUNK 36            // 72 / BCH
#define PLANE  132           // P_N*XT + 4 pad
#define TPLANE 130           // squash-tmp pad (conflict-free writes)
#define NSTG   5

#define STG_FL   (BCH * C_N * PLANE)      // 4224
#define U_FL     (NSTG * STG_FL)          // 21120
#define V_OFF    U_FL
#define V_FL     (C_N * PLANE)            // 2112
#define RECV_OFF (V_OFF + V_FL)
#define RECV_FL  1024                     // [c8][z][p]
#define SMEM_FL  (RECV_OFF + RECV_FL)     // 24256
#define SMEM_BYTES (SMEM_FL * 4)          // 97024 -> 2 CTAs/SM

#define V_ELEMS (8 * C_N * P_N * F2)      // 294912

__device__ __forceinline__ void cp_async16(uint32_t s, const float* g) {
    asm volatile("cp.async.cg.shared.global [%0], [%1], 16;" :: "r"(s), "l"(g));
}
__device__ __forceinline__ uint32_t mapa_u32(uint32_t a, uint32_t r) {
    uint32_t o;
    asm("mapa.shared::cluster.u32 %0, %1, %2;" : "=r"(o) : "r"(a), "r"(r));
    return o;
}
__device__ __forceinline__ void st_clu_v4(uint32_t a, float x, float y, float z, float w) {
    asm volatile("st.shared::cluster.v4.f32 [%0], {%1,%2,%3,%4};"
                 :: "r"(a), "f"(x), "f"(y), "f"(z), "f"(w) : "memory");
}
__device__ __forceinline__ void st_clu_f32(uint32_t a, float v) {
    asm volatile("st.shared::cluster.f32 [%0], %1;" :: "r"(a), "f"(v) : "memory");
}
#define CLUSTER_SYNC() do { \
    asm volatile("barrier.cluster.arrive.aligned;" ::: "memory"); \
    asm volatile("barrier.cluster.wait.aligned;"   ::: "memory"); } while (0)

// one B-chunk: BCH*C*P rows of 32B = 1024 x 16B, 4 cp.async per thread
__device__ __forceinline__ void prefetch_chunk(const float* __restrict__ ubB,
                                               uint32_t smb,
                                               int ch, int stg, int x0, int t) {
    uint32_t dst = smb + 4u * (stg * STG_FL);
    const float* g0 = ubB + (size_t)ch * BCH * C_N * P_N * F2;
#pragma unroll
    for (int k = 0; k < 4; k++) {
        int q  = t + k * 256;          // 0..1023
        int h  = q & 1;
        int pl = (q >> 1) & 15;
        int Cl = (q >> 5) & 15;
        int Bl = q >> 9;
        const float* g = g0 + ((size_t)(Bl * C_N + Cl) * P_N + pl) * F2 + x0 + h * 4;
        cp_async16(dst + 4u * ((Bl * C_N + Cl) * PLANE + pl * XT + h * 4), g);
    }
    asm volatile("cp.async.commit_group;");
}

__global__ void __cluster_dims__(2, 1, 1) __launch_bounds__(256, 2)
caps_route_kernel(const float* __restrict__ u, float* __restrict__ out) {
    extern __shared__ float sm[];
    const uint32_t smb = (uint32_t)__cvta_generic_to_shared(sm);
    float* u_s  = sm;
    float* v_s  = sm + V_OFF;
    float* recv = sm + RECV_OFF;
    float* tmp  = sm;                  // aliases stage 0 (pipeline drained)
    float* own  = sm + STG_FL;         // aliases stage 1

    const int t = threadIdx.x;
    uint32_t rank;
    asm("mov.u32 %0, %%cluster_ctarank;" : "=r"(rank));

    const unsigned unit = blockIdx.x >> 1;
    const int b    = unit / NTILE;
    const int tile = unit % NTILE;
    const int x0   = tile * XT;

    // CTA's B-half base pointer
    const float* ubB = u + (size_t)b * 144 * C_N * P_N * F2
                         + (size_t)rank * BHALF * C_N * P_N * F2;

    // compute mapping: t = Bl*128 + z*16 + Cc (C in 16-lane shuffle groups)
    const int Bl = t >> 7;
    const int z  = (t >> 4) & 7;
    const int Cc = t & 15;
    const int ubase_off = (Bl * C_N + Cc) * PLANE + z;

    float sreg[16], vreg[16];

    for (int pass = 0; pass < 3; pass++) {
#pragma unroll
        for (int i = 0; i < 16; i++) sreg[i] = 0.f;
        if (pass) {
#pragma unroll
            for (int p = 0; p < 16; p++) vreg[p] = v_s[Cc * PLANE + p * XT + z];
        }

#pragma unroll
        for (int k = 0; k < NSTG - 1; k++) prefetch_chunk(ubB, smb, k, k, x0, t);

        for (int ch = 0; ch < NCHUNK; ch++) {
            if      (ch <= NCHUNK - 4) asm volatile("cp.async.wait_group 3;");
            else if (ch == NCHUNK - 3) asm volatile("cp.async.wait_group 2;");
            else if (ch == NCHUNK - 2) asm volatile("cp.async.wait_group 1;");
            else                       asm volatile("cp.async.wait_group 0;");
            __syncthreads();   // chunk ch visible; stage (ch+4)%5 free

            if (ch + NSTG - 1 < NCHUNK)
                prefetch_chunk(ubB, smb, ch + NSTG - 1, (ch + NSTG - 1) % NSTG, x0, t);

            const float* base = u_s + (ch % NSTG) * STG_FL + ubase_off;
            float ureg[16];
#pragma unroll
            for (int p = 0; p < 16; p++) ureg[p] = base[p * XT];

            if (pass == 0) {
#pragma unroll
                for (int p = 0; p < 16; p++) sreg[p] += ureg[p];
            } else {
                float d0 = 0.f, d1 = 0.f;
#pragma unroll
                for (int p = 0; p < 16; p += 2) {
                    d0 = fmaf(ureg[p],     vreg[p],     d0);
                    d1 = fmaf(ureg[p + 1], vreg[p + 1], d1);
                }
                float rv = d0 + d1;
                float e = __expf(rv), ss = e;
#pragma unroll
                for (int m = 1; m < 16; m <<= 1)
                    ss += __shfl_xor_sync(0xffffffffu, ss, m);
                const float cc = __fdividef(e, ss);
#pragma unroll
                for (int p = 0; p < 16; p++) sreg[p] = fmaf(cc, ureg[p], sreg[p]);
            }
        }

        // ---- exchange + squash (pipeline drained; stages 0/1 reusable) ----
        const float w0 = (pass == 0) ? 0.0625f : 1.0f;
#pragma unroll
        for (int p = 0; p < 16; p++)
            tmp[(Bl * C_N + Cc) * TPLANE + p * 8 + z] = sreg[p] * w0;
        __syncthreads();

        {   // combine Bl halves; route C-half to owner (rank = Cc>>3)
            const int sz = t & 7, sC = (t >> 3) & 15, sp0 = (t >> 7) * 8;
            float sv[8];
#pragma unroll
            for (int i = 0; i < 8; i++)
                sv[i] = tmp[(sC)        * TPLANE + (sp0 + i) * 8 + sz]
                      + tmp[(C_N + sC)  * TPLANE + (sp0 + i) * 8 + sz];
            const int doff = ((sC & 7) * 8 + sz) * 16 + sp0;
            if ((uint32_t)(sC >> 3) == rank) {
                *(float4*)(own + doff)     = make_float4(sv[0], sv[1], sv[2], sv[3]);
                *(float4*)(own + doff + 4) = make_float4(sv[4], sv[5], sv[6], sv[7]);
            } else {
                uint32_t rad = mapa_u32(smb + 4u * (RECV_OFF + doff), rank ^ 1u);
                st_clu_v4(rad,      sv[0], sv[1], sv[2], sv[3]);
                st_clu_v4(rad + 16, sv[4], sv[5], sv[6], sv[7]);
            }
        }
        CLUSTER_SYNC();

        {   // owner reduce + squash for C = rank*8 + c8
            const int c8 = t >> 5, qz = (t >> 2) & 7, pq = t & 3;
            const int off = (c8 * 8 + qz) * 16 + pq * 4;
            float4 o4 = *(float4*)(own + off);
            float4 r4 = *(float4*)(recv + off);
            float s0 = o4.x + r4.x, s1 = o4.y + r4.y,
                  s2 = o4.z + r4.z, s3 = o4.w + r4.w;
            float sn = s0 * s0 + s1 * s1 + s2 * s2 + s3 * s3;
            sn += __shfl_xor_sync(0xffffffffu, sn, 1);
            sn += __shfl_xor_sync(0xffffffffu, sn, 2);
            const float scale = sqrtf(sn) / (1.f + sn);
            const int Cl = (int)rank * 8 + c8;
            float sv4[4] = {s0, s1, s2, s3};

            if (pass < 2) {
#pragma unroll
                for (int i = 0; i < 4; i++) {
                    const int p = pq * 4 + i;
                    float vo = (pass == 1) ? v_s[Cl * PLANE + p * XT + qz] : 0.f;
                    float vn = vo + sv4[i] * scale;   // pass1 stores w = v0+v1
                    uint32_t loc = smb + 4u * (V_OFF + Cl * PLANE + p * XT + qz);
                    st_clu_f32(mapa_u32(loc, 0u), vn);
                    st_clu_f32(mapa_u32(loc, 1u), vn);
                }
            } else {
#pragma unroll
                for (int i = 0; i < 4; i++) {
                    const int p = pq * 4 + i;
                    out[(((size_t)(b * C_N + Cl)) * P_N + p) * F2 + x0 + qz] =
                        sv4[i] * scale;
                }
                if (pq == 0)
                    out[(size_t)V_ELEMS + ((size_t)(b * C_N + Cl)) * F2 + x0 + qz] =
                        sn / (1.f + sn);
            }
        }
        CLUSTER_SYNC();   // v visible everywhere; recv free for next pass
    }
}

extern "C" void kernel_launch(void* const* d_in, const int* in_sizes, int n_in,
                              void* d_out, int out_size) {
    const float* u = (const float*)d_in[0];   // (8,144,16,16,12,12) f32
    float* out = (float*)d_out;               // v (8,16,16,144) then a_out (8,16,144)

    cudaFuncSetAttribute(caps_route_kernel,
                         cudaFuncAttributeMaxDynamicSharedMemorySize, SMEM_BYTES);
    caps_route_kernel<<<8 * NTILE * 2, 256, SMEM_BYTES>>>(u, out);
}

// round 8
// speedup vs baseline: 1.4157x; 1.2488x over previous
#include <cuda_runtime.h>
#include <cstdint>

// CapsuleRouting R7: barrier-free per-warp pipelines, 1 CTA/SM
//  - CTA = (b, x-tile of 8); 144 CTAs, 256 threads
//  - warp w owns B = w*18..w*18+17, private 3-stage cp.async pipeline
//    (per-thread cp.async groups -> no __syncthreads in main loop)
//  - lane = (zh, Cc): float4 LDS (conflict-free), 4 z-chains per lane
//  - r eliminated (logits linear in v: pass2 dots against w = v0+v1)
//  - `a` input cancels in softmax -> ignored

#define C_N   16
#define P_N   16
#define F2    144
#define XT    8
#define NTILE 18
#define NW    8
#define BPW   18                    // B per warp
#define PLANE 132                   // P_N*XT + 4 pad
#define STG_FL (C_N * PLANE)        // 2112 floats per stage (one B)
#define NSTG  3
#define WSTRIDE (NSTG * STG_FL)     // 6336 per warp
#define U_FL  (NW * WSTRIDE)        // 50688
#define V_OFF U_FL
#define SMEM_FL (U_FL + STG_FL)     // 52800
#define SMEM_BYTES (SMEM_FL * 4)    // 211200 -> 1 CTA/SM
#define BSTRIDE (C_N * P_N * F2)    // 36864 floats per B
#define V_ELEMS (8 * C_N * P_N * F2)

__device__ __forceinline__ void cp_async16(uint32_t s, const float* g) {
    asm volatile("cp.async.cg.shared.global [%0], [%1], 16;" :: "r"(s), "l"(g));
}

// load one B-value (16C x 16p rows of 32B) into a warp stage; 16 cp.async/lane
__device__ __forceinline__ void prefetch_B(const float* __restrict__ gB,
                                           uint32_t dst, int lane) {
    const int pl = lane >> 1, h = lane & 1;
    const float* g = gB + (size_t)pl * F2 + h * 4;
    uint32_t d = dst + 4u * (pl * XT + h * 4);
#pragma unroll
    for (int k = 0; k < 16; k++)     // k = C index
        cp_async16(d + 4u * (k * PLANE), g + (size_t)k * (P_N * F2));
    asm volatile("cp.async.commit_group;");
}

__global__ void __launch_bounds__(256, 1)
caps_route_kernel(const float* __restrict__ u, float* __restrict__ out) {
    extern __shared__ float sm[];
    const uint32_t smb = (uint32_t)__cvta_generic_to_shared(sm);
    float* v_s = sm + V_OFF;

    const int t = threadIdx.x;
    const int w = t >> 5, lane = t & 31;
    const int Cc = lane & 15, zh = lane >> 4;      // zh: z-quad 0..3 / 4..7

    const int b  = blockIdx.x / NTILE;
    const int x0 = (blockIdx.x % NTILE) * XT;

    // warp's B-slice base (x0 folded in)
    const float* ubW = u + ((size_t)b * 144 + w * BPW) * BSTRIDE + x0;
    const uint32_t wbase = smb + 4u * (w * WSTRIDE);
    float* wstage0 = sm + w * WSTRIDE;

    const int ld_off = Cc * PLANE + zh * 4;        // + p*8 for each p

    for (int pass = 0; pass < 3; pass++) {
        float4 vreg[16];
        if (pass) {
#pragma unroll
            for (int p = 0; p < 16; p++)
                vreg[p] = *(const float4*)&v_s[ld_off + p * 8];
        }
        float4 sreg[16];
#pragma unroll
        for (int p = 0; p < 16; p++) sreg[p] = make_float4(0.f, 0.f, 0.f, 0.f);

        prefetch_B(ubW,            wbase,                 lane);
        prefetch_B(ubW + BSTRIDE,  wbase + 4u * STG_FL,   lane);

        for (int j = 0; j < BPW; j++) {
            if (j + 2 < BPW)
                prefetch_B(ubW + (size_t)(j + 2) * BSTRIDE,
                           wbase + 4u * (((j + 2) % NSTG) * STG_FL), lane);
            // per-warp pacing, no block barrier
            if      (j <= BPW - 3) asm volatile("cp.async.wait_group 2;");
            else if (j == BPW - 2) asm volatile("cp.async.wait_group 1;");
            else                   asm volatile("cp.async.wait_group 0;");
            __syncwarp();

            const float* st = sm + w * WSTRIDE + (j % NSTG) * STG_FL + ld_off;

            if (pass == 0) {
#pragma unroll
                for (int p = 0; p < 16; p++) {
                    float4 u4 = *(const float4*)&st[p * 8];
                    sreg[p].x += u4.x; sreg[p].y += u4.y;
                    sreg[p].z += u4.z; sreg[p].w += u4.w;
                }
            } else {
                float4 d = make_float4(0.f, 0.f, 0.f, 0.f);
#pragma unroll
                for (int p = 0; p < 16; p++) {
                    float4 u4 = *(const float4*)&st[p * 8];
                    d.x = fmaf(u4.x, vreg[p].x, d.x);
                    d.y = fmaf(u4.y, vreg[p].y, d.y);
                    d.z = fmaf(u4.z, vreg[p].z, d.z);
                    d.w = fmaf(u4.w, vreg[p].w, d.w);
                }
                // softmax over C: 16-lane shuffle groups, 4 chains ILP
                float4 e = make_float4(__expf(d.x), __expf(d.y),
                                       __expf(d.z), __expf(d.w));
                float4 ss = e;
#pragma unroll
                for (int m = 1; m < 16; m <<= 1) {
                    ss.x += __shfl_xor_sync(0xffffffffu, ss.x, m);
                    ss.y += __shfl_xor_sync(0xffffffffu, ss.y, m);
                    ss.z += __shfl_xor_sync(0xffffffffu, ss.z, m);
                    ss.w += __shfl_xor_sync(0xffffffffu, ss.w, m);
                }
                float4 cc = make_float4(__fdividef(e.x, ss.x),
                                        __fdividef(e.y, ss.y),
                                        __fdividef(e.z, ss.z),
                                        __fdividef(e.w, ss.w));
#pragma unroll
                for (int p = 0; p < 16; p++) {
                    float4 u4 = *(const float4*)&st[p * 8];
                    sreg[p].x = fmaf(cc.x, u4.x, sreg[p].x);
                    sreg[p].y = fmaf(cc.y, u4.y, sreg[p].y);
                    sreg[p].z = fmaf(cc.z, u4.z, sreg[p].z);
                    sreg[p].w = fmaf(cc.w, u4.w, sreg[p].w);
                }
            }
        }

        // ---- per-warp partial s -> own stage 0 (own pipeline drained) ----
        if (pass == 0) {
#pragma unroll
            for (int p = 0; p < 16; p++) {
                sreg[p].x *= 0.0625f; sreg[p].y *= 0.0625f;
                sreg[p].z *= 0.0625f; sreg[p].w *= 0.0625f;
            }
        }
#pragma unroll
        for (int p = 0; p < 16; p++)
            *(float4*)&wstage0[ld_off + p * 8] = sreg[p];
        __syncthreads();

        // ---- cross-warp reduce + squash: thread t = (Cc2 = t>>4, p2 = t&15)
        {
            const int Cc2 = t >> 4, p2 = t & 15;
            const int roff = Cc2 * PLANE + p2 * 8;
            float4 sa = make_float4(0.f, 0.f, 0.f, 0.f);   // z 0..3
            float4 sb = make_float4(0.f, 0.f, 0.f, 0.f);   // z 4..7
#pragma unroll
            for (int w2 = 0; w2 < NW; w2++) {
                float4 a4 = *(const float4*)&sm[w2 * WSTRIDE + roff];
                float4 b4 = *(const float4*)&sm[w2 * WSTRIDE + roff + 4];
                sa.x += a4.x; sa.y += a4.y; sa.z += a4.z; sa.w += a4.w;
                sb.x += b4.x; sb.y += b4.y; sb.z += b4.z; sb.w += b4.w;
            }
            // sn per (C,z): reduce s^2 over 16 p-lanes (bits 0-3 of t)
            float4 na = make_float4(sa.x * sa.x, sa.y * sa.y,
                                    sa.z * sa.z, sa.w * sa.w);
            float4 nb = make_float4(sb.x * sb.x, sb.y * sb.y,
                                    sb.z * sb.z, sb.w * sb.w);
#pragma unroll
            for (int m = 1; m < 16; m <<= 1) {
                na.x += __shfl_xor_sync(0xffffffffu, na.x, m);
                na.y += __shfl_xor_sync(0xffffffffu, na.y, m);
                na.z += __shfl_xor_sync(0xffffffffu, na.z, m);
                na.w += __shfl_xor_sync(0xffffffffu, na.w, m);
                nb.x += __shfl_xor_sync(0xffffffffu, nb.x, m);
                nb.y += __shfl_xor_sync(0xffffffffu, nb.y, m);
                nb.z += __shfl_xor_sync(0xffffffffu, nb.z, m);
                nb.w += __shfl_xor_sync(0xffffffffu, nb.w, m);
            }
            float4 ka = make_float4(sqrtf(na.x) / (1.f + na.x),
                                    sqrtf(na.y) / (1.f + na.y),
                                    sqrtf(na.z) / (1.f + na.z),
                                    sqrtf(na.w) / (1.f + na.w));
            float4 kb = make_float4(sqrtf(nb.x) / (1.f + nb.x),
                                    sqrtf(nb.y) / (1.f + nb.y),
                                    sqrtf(nb.z) / (1.f + nb.z),
                                    sqrtf(nb.w) / (1.f + nb.w));
            float4 va = make_float4(sa.x * ka.x, sa.y * ka.y,
                                    sa.z * ka.z, sa.w * ka.w);
            float4 vb = make_float4(sb.x * kb.x, sb.y * kb.y,
                                    sb.z * kb.z, sb.w * kb.w);

            if (pass < 2) {
                if (pass == 1) {   // store w = v0 + v1 (logits linear in v)
                    float4 oa = *(const float4*)&v_s[roff];
                    float4 ob = *(const float4*)&v_s[roff + 4];
                    va.x += oa.x; va.y += oa.y; va.z += oa.z; va.w += oa.w;
                    vb.x += ob.x; vb.y += ob.y; vb.z += ob.z; vb.w += ob.w;
                }
                *(float4*)&v_s[roff]     = va;
                *(float4*)&v_s[roff + 4] = vb;
            } else {
                float* og = out + (((size_t)(b * C_N + Cc2)) * P_N + p2) * F2 + x0;
                *(float4*)og       = va;
                *(float4*)(og + 4) = vb;
                if (p2 == 0) {
                    float* oa = out + (size_t)V_ELEMS
                              + ((size_t)(b * C_N + Cc2)) * F2 + x0;
                    *(float4*)oa = make_float4(na.x / (1.f + na.x),
                                               na.y / (1.f + na.y),
                                               na.z / (1.f + na.z),
                                               na.w / (1.f + na.w));
                    *(float4*)(oa + 4) = make_float4(nb.x / (1.f + nb.x),
                                                     nb.y / (1.f + nb.y),
                                                     nb.z / (1.f + nb.z),
                                                     nb.w / (1.f + nb.w));
                }
            }
        }
        __syncthreads();   // v visible; stage-0 partials consumed before reuse
    }
}

extern "C" void kernel_launch(void* const* d_in, const int* in_sizes, int n_in,
                              void* d_out, int out_size) {
    const float* u = (const float*)d_in[0];   // (8,144,16,16,12,12) f32
    float* out = (float*)d_out;               // v (8,16,16,144) then a_out (8,16,144)

    cudaFuncSetAttribute(caps_route_kernel,
                         cudaFuncAttributeMaxDynamicSharedMemorySize, SMEM_BYTES);
    caps_route_kernel<<<8 * NTILE, 256, SMEM_BYTES>>>(u, out);
}